// round 3
// baseline (speedup 1.0000x reference)
#include <cuda_runtime.h>
#include <cuda_bf16.h>

// DensityEstimator: per-channel 1->3->3->3->1 MLP, p = cdf(x+.5) - cdf(x-.5)
// R3: single-wave grid (576 blocks = 4/SM reg-limited residency, one wave,
// channel-invariant since 576*256 = 192*768), tanh-form epilogue
// sigma(fp)-sigma(fm) = 0.5*(tanh(fp/2)-tanh(fm/2)) with the 1/2 folded into
// the precomputed layer-3 weights. 20 MUFU/elem.

#define NCH 192
#define NBLK 576          // 576*256 = 147456 = 192*768 -> channel invariant; one wave
#define NTHR 256

__device__ __forceinline__ float tanha(float x) {
    float r; asm("tanh.approx.f32 %0, %1;" : "=f"(r) : "f"(x)); return r;
}

// Accurate softplus for the one-time weight transform.
__device__ __forceinline__ float softplus_acc(float h) {
    return (h > 15.0f) ? h : log1pf(expf(h));
}

__global__ void __launch_bounds__(NTHR, 4) de_kernel(
    const float* __restrict__ x,
    const float* __restrict__ a0, const float* __restrict__ a1, const float* __restrict__ a2,
    const float* __restrict__ b0, const float* __restrict__ b1, const float* __restrict__ b2,
    const float* __restrict__ b3,
    const float* __restrict__ H0, const float* __restrict__ H1, const float* __restrict__ H2,
    const float* __restrict__ H3,
    float* __restrict__ out, int n)
{
    const int stride = gridDim.x * blockDim.x;      // multiple of 192
    const int i0 = blockIdx.x * blockDim.x + threadIdx.x;
    const int c  = i0 % NCH;                        // fixed channel for this thread

    // One-time per-thread weight transform into registers.
    float sh0[3], sh1[9], sh2[9], sh3[3];
    float ta0[3], ta1[3], ta2[3];
    float bp0[3], bm0[3], bb1[3], bb2[3], bb3;
#pragma unroll
    for (int j = 0; j < 3; j++) {
        sh0[j] = softplus_acc(__ldg(&H0[c*3 + j]));          // H0: (C,1,3)
        sh3[j] = 0.5f * softplus_acc(__ldg(&H3[c*3 + j]));   // H3: (C,3,1), 1/2 folded
        ta0[j] = tanhf(__ldg(&a0[c*3 + j]));
        ta1[j] = tanhf(__ldg(&a1[c*3 + j]));
        ta2[j] = tanhf(__ldg(&a2[c*3 + j]));
        float b0j = __ldg(&b0[c*3 + j]);
        bp0[j] = fmaf( 0.5f, sh0[j], b0j);                   // fold x+0.5 into bias
        bm0[j] = fmaf(-0.5f, sh0[j], b0j);                   // fold x-0.5 into bias
        bb1[j] = __ldg(&b1[c*3 + j]);
        bb2[j] = __ldg(&b2[c*3 + j]);
    }
#pragma unroll
    for (int j = 0; j < 9; j++) {
        sh1[j] = softplus_acc(__ldg(&H1[c*9 + j]));          // H1: (C,3,3) [i*3+p]
        sh2[j] = softplus_acc(__ldg(&H2[c*9 + j]));
    }
    bb3 = 0.5f * __ldg(&b3[c]);                              // 1/2 folded

    for (int i = i0; i < n; i += stride) {
        float xv = x[i];

        // Layer 0: 1 -> 3 (shifted biases absorb the +-0.5)
        float yp[3], ym[3];
#pragma unroll
        for (int j = 0; j < 3; j++) {
            float tp = fmaf(xv, sh0[j], bp0[j]);
            float tm = fmaf(xv, sh0[j], bm0[j]);
            yp[j] = fmaf(ta0[j], tanha(tp), tp);
            ym[j] = fmaf(ta0[j], tanha(tm), tm);
        }

        // Layer 1: 3 -> 3
        float zp[3], zm[3];
#pragma unroll
        for (int p = 0; p < 3; p++) {
            float sp = bb1[p], sm = bb1[p];
#pragma unroll
            for (int j = 0; j < 3; j++) {
                sp = fmaf(yp[j], sh1[j*3 + p], sp);
                sm = fmaf(ym[j], sh1[j*3 + p], sm);
            }
            zp[p] = fmaf(ta1[p], tanha(sp), sp);
            zm[p] = fmaf(ta1[p], tanha(sm), sm);
        }

        // Layer 2: 3 -> 3
#pragma unroll
        for (int p = 0; p < 3; p++) {
            float sp = bb2[p], sm = bb2[p];
#pragma unroll
            for (int j = 0; j < 3; j++) {
                sp = fmaf(zp[j], sh2[j*3 + p], sp);
                sm = fmaf(zm[j], sh2[j*3 + p], sm);
            }
            yp[p] = fmaf(ta2[p], tanha(sp), sp);
            ym[p] = fmaf(ta2[p], tanha(sm), sm);
        }

        // Layer 3: 3 -> 1 with the 1/2 pre-folded, then
        // sigma(fp)-sigma(fm) = 0.5*(tanh(fp/2) - tanh(fm/2))
        float fp = bb3, fm = bb3;
#pragma unroll
        for (int j = 0; j < 3; j++) {
            fp = fmaf(yp[j], sh3[j], fp);
            fm = fmaf(ym[j], sh3[j], fm);
        }
        out[i] = 0.5f * (tanha(fp) - tanha(fm));
    }
}

extern "C" void kernel_launch(void* const* d_in, const int* in_sizes, int n_in,
                              void* d_out, int out_size)
{
    const float* x  = (const float*)d_in[0];
    const float* a0 = (const float*)d_in[1];
    const float* a1 = (const float*)d_in[2];
    const float* a2 = (const float*)d_in[3];
    const float* b0 = (const float*)d_in[4];
    const float* b1 = (const float*)d_in[5];
    const float* b2 = (const float*)d_in[6];
    const float* b3 = (const float*)d_in[7];
    const float* H0 = (const float*)d_in[8];
    const float* H1 = (const float*)d_in[9];
    const float* H2 = (const float*)d_in[10];
    const float* H3 = (const float*)d_in[11];
    float* out = (float*)d_out;
    int n = in_sizes[0];   // 65536 * 192

    de_kernel<<<NBLK, NTHR>>>(x, a0, a1, a2, b0, b1, b2, b3,
                              H0, H1, H2, H3, out, n);
}